// round 15
// baseline (speedup 1.0000x reference)
#include <cuda_runtime.h>
#include <cstdint>

// ---------------- problem constants ----------------
#define TSTEPS 16384
#define INDIM  512
#define HDIM   1024
#define G4     4096      // 4*HDIM
#define OUTDIM 64
#define NCTA   128       // persistent CTAs (<= 148 SMs -> all co-resident)

// ---------------- device globals (sanctioned scratch) ----------------
__device__ __align__(16) float g_xp[(size_t)TSTEPS * G4];  // xproj, STANDARD layout [t][g*1024+n]
// per-CTA publication line: words 0..7 = h fp32 bits, word 8 = flag, pad to 128B
__device__ __align__(128) unsigned g_pub[2][NCTA][32];

// ---------------- helpers ----------------
__device__ __forceinline__ float4 ld_cg_f4(const float4* p) {
    float4 v;
    asm volatile("ld.global.cg.v4.f32 {%0,%1,%2,%3}, [%4];"
                 : "=f"(v.x), "=f"(v.y), "=f"(v.z), "=f"(v.w) : "l"(p) : "memory");
    return v;
}
__device__ __forceinline__ void st_cg_f4(float* p, float4 v) {
    asm volatile("st.global.cg.v4.f32 [%0], {%1,%2,%3,%4};"
                 :: "l"(p), "f"(v.x), "f"(v.y), "f"(v.z), "f"(v.w) : "memory");
}
__device__ __forceinline__ unsigned ld_rlx(const unsigned* p) {
    unsigned v;
    asm volatile("ld.relaxed.gpu.b32 %0, [%1];" : "=r"(v) : "l"(p) : "memory");
    return v;
}
__device__ __forceinline__ void fence_acq() {
    asm volatile("fence.acq_rel.gpu;" ::: "memory");
}
__device__ __forceinline__ void st_rel(unsigned* p, unsigned v) {
    asm volatile("st.release.gpu.b32 [%0], %1;" :: "l"(p), "r"(v) : "memory");
}
// packed f32x2 ops (Blackwell; arithmetic exonerated by R4/R5 bisect)
__device__ __forceinline__ unsigned long long pk2(float x, float y) {
    unsigned long long r;
    asm("mov.b64 %0, {%1, %2};" : "=l"(r) : "f"(x), "f"(y));
    return r;
}
__device__ __forceinline__ void upk2(unsigned long long v, float& x, float& y) {
    asm("mov.b64 {%0, %1}, %2;" : "=f"(x), "=f"(y) : "l"(v));
}
__device__ __forceinline__ unsigned long long fma2(unsigned long long a,
                                                   unsigned long long b,
                                                   unsigned long long c) {
    unsigned long long d;
    asm("fma.rn.f32x2 %0, %1, %2, %3;" : "=l"(d) : "l"(a), "l"(b), "l"(c));
    return d;
}
// fast activations (MUFU-based; validated passing at 3.6e-7)
__device__ __forceinline__ float sigf(float x) {
    return __fdividef(1.0f, 1.0f + __expf(-x));
}
__device__ __forceinline__ float tanh_f(float x) {
    float a = fabsf(x);
    float e = __expf(-2.0f * a);
    float t = __fdividef(1.0f - e, 1.0f + e);
    return copysignf(t, x);
}

// Pick X among three same-sized candidates (content-based, deterministic)
__device__ __forceinline__ const float* pick_x(const float* a, const float* b,
                                               const float* c) {
    bool na = false, nb = false;
    for (int i = 0; i < 64; i++) { na |= (a[i] < 0.0f); nb |= (b[i] < 0.0f); }
    return na ? a : (nb ? b : c);
}

// =====================================================================
// Kernel 1: xproj GEMM, STANDARD layout (unchanged from passing rounds).
// =====================================================================
__global__ __launch_bounds__(256, 2) void xproj_kernel(
    const float* __restrict__ xc0, const float* __restrict__ xc1,
    const float* __restrict__ xc2, const float* __restrict__ Wih,
    const float* __restrict__ b0, const float* __restrict__ b1)
{
    __shared__ float As[8][128];
    __shared__ float Bs[8][128];

    const float* X = pick_x(xc0, xc1, xc2);

    const int tid = threadIdx.x;
    const int tx = tid & 15;
    const int ty = tid >> 4;
    const int t0 = blockIdx.y * 128;
    const int R0 = blockIdx.x * 128;

    const int lrow = tid >> 1;
    const int lk4  = (tid & 1) * 4;
    const float* pA = X   + (size_t)(t0 + lrow) * INDIM + lk4;
    const float* pB = Wih + (size_t)(R0 + lrow) * INDIM + lk4;

    float acc[8][8];
    #pragma unroll
    for (int i = 0; i < 8; i++)
        #pragma unroll
        for (int j = 0; j < 8; j++) acc[i][j] = 0.0f;

    float4 ra = *(const float4*)pA;
    float4 rb = *(const float4*)pB;

    for (int k0 = 0; k0 < INDIM; k0 += 8) {
        __syncthreads();
        As[lk4 + 0][lrow] = ra.x; As[lk4 + 1][lrow] = ra.y;
        As[lk4 + 2][lrow] = ra.z; As[lk4 + 3][lrow] = ra.w;
        Bs[lk4 + 0][lrow] = rb.x; Bs[lk4 + 1][lrow] = rb.y;
        Bs[lk4 + 2][lrow] = rb.z; Bs[lk4 + 3][lrow] = rb.w;
        __syncthreads();
        if (k0 + 8 < INDIM) {
            ra = *(const float4*)(pA + k0 + 8);
            rb = *(const float4*)(pB + k0 + 8);
        }
        #pragma unroll
        for (int kk = 0; kk < 8; kk++) {
            float a[8], b[8];
            *(float4*)&a[0] = *(const float4*)&As[kk][ty * 8];
            *(float4*)&a[4] = *(const float4*)&As[kk][ty * 8 + 4];
            *(float4*)&b[0] = *(const float4*)&Bs[kk][tx * 8];
            *(float4*)&b[4] = *(const float4*)&Bs[kk][tx * 8 + 4];
            #pragma unroll
            for (int i = 0; i < 8; i++)
                #pragma unroll
                for (int j = 0; j < 8; j++)
                    acc[i][j] = fmaf(a[i], b[j], acc[i][j]);
        }
    }

    const int Rc = R0 + tx * 8;
    float bias[8];
    #pragma unroll
    for (int j = 0; j < 8; j++) bias[j] = b0[Rc + j] + b1[Rc + j];

    #pragma unroll
    for (int i = 0; i < 8; i++) {
        float v[8];
        #pragma unroll
        for (int j = 0; j < 8; j++) v[j] = acc[i][j] + bias[j];
        float* dst = g_xp + (size_t)(t0 + ty * 8 + i) * G4 + Rc;
        *(float4*)(dst)     = make_float4(v[0], v[1], v[2], v[3]);
        *(float4*)(dst + 4) = make_float4(v[4], v[5], v[6], v[7]);
    }
}

// =====================================================================
// Kernel 2: persistent recurrence. 128 CTAs x 256 threads.
// R12 protocol skeleton (validated) + f32x2 dots + relaxed-poll/acquire-
// fence detection. Warp sums via the validated SHFL butterfly (REDUX.f32
// does not exist on sm_103).
// =====================================================================
__global__ __launch_bounds__(256, 1) void rnn_kernel(
    const float* __restrict__ Whh, const float* __restrict__ Wlin,
    const float* __restrict__ blin, float* __restrict__ out)
{
    __shared__ float smh[HDIM];   // h_{t-1}, identity layout
    __shared__ float hpub[8];     // this CTA's 8 fresh h values

    const int tid = threadIdx.x;
    const int w = tid >> 5, l = tid & 31;
    const int n = blockIdx.x * 8 + w;

    // ---- load W_hh, pre-packed as f32x2 pairs ----
    // lane l covers cols {4l,4l+1} (pair A) and {4l+2,4l+3} (pair B) + 128j
    unsigned long long wA0[8], wB0[8], wA1[8], wB1[8],
                       wA2[8], wB2[8], wA3[8], wB3[8];
    {
        const float* r0 = Whh + (size_t)(0 * HDIM + n) * HDIM + 4 * l;
        const float* r1 = Whh + (size_t)(1 * HDIM + n) * HDIM + 4 * l;
        const float* r2 = Whh + (size_t)(2 * HDIM + n) * HDIM + 4 * l;
        const float* r3 = Whh + (size_t)(3 * HDIM + n) * HDIM + 4 * l;
        #pragma unroll
        for (int j = 0; j < 8; j++) {
            float4 q;
            q = __ldg((const float4*)(r0 + 128 * j));
            wA0[j] = pk2(q.x, q.y); wB0[j] = pk2(q.z, q.w);
            q = __ldg((const float4*)(r1 + 128 * j));
            wA1[j] = pk2(q.x, q.y); wB1[j] = pk2(q.z, q.w);
            q = __ldg((const float4*)(r2 + 128 * j));
            wA2[j] = pk2(q.x, q.y); wB2[j] = pk2(q.z, q.w);
            q = __ldg((const float4*)(r3 + 128 * j));
            wA3[j] = pk2(q.x, q.y); wB3[j] = pk2(q.z, q.w);
        }
    }

    smh[tid] = 0.0f; smh[tid + 256] = 0.0f;
    smh[tid + 512] = 0.0f; smh[tid + 768] = 0.0f;   // h_{-1} = 0
    float c = 0.0f;

    // prefetch xp for t=0 (lane 0 of each warp)
    float xi = 0.f, xf = 0.f, xg = 0.f, xo = 0.f;
    if (l == 0) {
        const float* xb = g_xp + n;
        xi = __ldcg(xb);
        xf = __ldcg(xb + HDIM);
        xg = __ldcg(xb + 2 * HDIM);
        xo = __ldcg(xb + 3 * HDIM);
    }
    __syncthreads();

    for (int t = 0; t < TSTEPS; t++) {
        // issue next step's xp prefetch (overlaps dots + sync below)
        float nxi = 0.f, nxf = 0.f, nxg = 0.f, nxo = 0.f;
        if (l == 0 && t + 1 < TSTEPS) {
            const float* xb = g_xp + (size_t)(t + 1) * G4 + n;
            nxi = __ldcg(xb);
            nxf = __ldcg(xb + HDIM);
            nxg = __ldcg(xb + 2 * HDIM);
            nxo = __ldcg(xb + 3 * HDIM);
        }

        // 4 gate dot-products, f32x2: 8x LDS.128, 64 fma2 (2 accums/gate)
        unsigned long long a0A = 0, a0B = 0, a1A = 0, a1B = 0,
                           a2A = 0, a2B = 0, a3A = 0, a3B = 0;
        #pragma unroll
        for (int j = 0; j < 8; j++) {
            float4 h4 = *(const float4*)&smh[4 * l + 128 * j];
            unsigned long long h2a = pk2(h4.x, h4.y);
            unsigned long long h2b = pk2(h4.z, h4.w);
            a0A = fma2(wA0[j], h2a, a0A); a0B = fma2(wB0[j], h2b, a0B);
            a1A = fma2(wA1[j], h2a, a1A); a1B = fma2(wB1[j], h2b, a1B);
            a2A = fma2(wA2[j], h2a, a2A); a2B = fma2(wB2[j], h2b, a2B);
            a3A = fma2(wA3[j], h2a, a3A); a3B = fma2(wB3[j], h2b, a3B);
        }
        float s0, s1, s2, s3, ux, uy, vx, vy;
        upk2(a0A, ux, uy); upk2(a0B, vx, vy); s0 = (ux + uy) + (vx + vy);
        upk2(a1A, ux, uy); upk2(a1B, vx, vy); s1 = (ux + uy) + (vx + vy);
        upk2(a2A, ux, uy); upk2(a2B, vx, vy); s2 = (ux + uy) + (vx + vy);
        upk2(a3A, ux, uy); upk2(a3B, vx, vy); s3 = (ux + uy) + (vx + vy);

        // warp sums: validated SHFL butterfly (4 independent chains pipeline)
        #pragma unroll
        for (int off = 16; off > 0; off >>= 1) {
            s0 += __shfl_xor_sync(0xffffffffu, s0, off);
            s1 += __shfl_xor_sync(0xffffffffu, s1, off);
            s2 += __shfl_xor_sync(0xffffffffu, s2, off);
            s3 += __shfl_xor_sync(0xffffffffu, s3, off);
        }

        // activations (warp-redundant; xp broadcast from lane 0)
        float gi = sigf(s0 + __shfl_sync(0xffffffffu, xi, 0));
        float gf = sigf(s1 + __shfl_sync(0xffffffffu, xf, 0));
        float gg = tanh_f(s2 + __shfl_sync(0xffffffffu, xg, 0));
        float go = sigf(s3 + __shfl_sync(0xffffffffu, xo, 0));
        c = gf * c + gi * gg;
        float hn = go * tanh_f(c);

        if (l == 0) hpub[w] = hn;
        __syncthreads();                 // smh reads done AND hpub complete

        // tid0 publishes the CTA's 8 h + release flag on ONE 128B line
        // (tid0 issues ALL global data stores -> its release orders them)
        if (tid == 0) {
            unsigned* base = &g_pub[t & 1][blockIdx.x][0];
            float4 a = *(const float4*)&hpub[0];
            float4 b = *(const float4*)&hpub[4];
            st_cg_f4((float*)base, a);
            st_cg_f4((float*)(base + 4), b);
            st_rel(base + 8, (unsigned)(t + 1));
        }

        // threads 0..127: relaxed-poll source CTA (=tid)'s flag, acquire
        // fence after detection, then load that line's 8 h (L2-hot)
        if (tid < NCTA) {
            const unsigned* base = &g_pub[t & 1][tid][0];
            while (ld_rlx(base + 8) != (unsigned)(t + 1)) { }
            fence_acq();
            float4 a = ld_cg_f4((const float4*)base);
            float4 b = ld_cg_f4((const float4*)(base + 4));
            *(float4*)&smh[8 * tid]     = a;
            *(float4*)&smh[8 * tid + 4] = b;
        }
        __syncthreads();                 // smh complete for next step

        xi = nxi; xf = nxf; xg = nxg; xo = nxo;
    }

    // ---- final linear + sigmoid on CTA 0 (smh holds h_{T-1}) ----
    if (blockIdx.x == 0) {
        #pragma unroll 1
        for (int o = w; o < OUTDIM; o += 8) {
            const float* wl = Wlin + (size_t)o * HDIM;
            float acc = 0.0f;
            #pragma unroll
            for (int j = 0; j < 32; j++) {
                int k = l + 32 * j;
                acc = fmaf(wl[k], smh[k], acc);
            }
            #pragma unroll
            for (int off = 16; off > 0; off >>= 1)
                acc += __shfl_xor_sync(0xffffffffu, acc, off);
            if (l == 0)
                out[o] = __fdividef(1.0f, 1.0f + __expf(-(acc + blin[o])));
        }
    }
}

// =====================================================================
// Host: resolve inputs BY SIZE (ordering-proof).
// =====================================================================
extern "C" void kernel_launch(void* const* d_in, const int* in_sizes, int n_in,
                              void* d_out, int out_size)
{
    const float* cand[3] = {nullptr, nullptr, nullptr};
    int nc = 0;
    const float* Wih = nullptr;
    const float* Whh = nullptr;
    const float* bsum[2] = {nullptr, nullptr};
    int nb = 0;
    const float* Wlin = nullptr;
    const float* blin = nullptr;

    for (int i = 0; i < n_in; i++) {
        const float* p = (const float*)d_in[i];
        switch (in_sizes[i]) {
            case 8388608: if (nc < 3) cand[nc++] = p; break;
            case 2097152: Wih = p; break;
            case 4194304: Whh = p; break;
            case 4096:    if (nb < 2) bsum[nb++] = p; break;
            case 65536:   Wlin = p; break;
            case 64:      blin = p; break;
            default: break; // dt (16384) unused
        }
    }
    float* out = (float*)d_out;

    dim3 ggrid(G4 / 128, TSTEPS / 128);       // 32 x 128 tiles
    xproj_kernel<<<ggrid, 256>>>(cand[0], cand[1], cand[2], Wih, bsum[0], bsum[1]);
    rnn_kernel<<<NCTA, 256>>>(Whh, Wlin, blin, out);
}

// round 16
// speedup vs baseline: 1.4496x; 1.4496x over previous
#include <cuda_runtime.h>
#include <cstdint>

// ---------------- problem constants ----------------
#define TSTEPS 16384
#define INDIM  512
#define HDIM   1024
#define G4     4096      // 4*HDIM
#define OUTDIM 64
#define NCTA   128       // persistent CTAs (<= 148 SMs -> all co-resident)

// ---------------- device globals (sanctioned scratch) ----------------
__device__ __align__(16) float g_xp[(size_t)TSTEPS * G4];  // xproj, STANDARD layout [t][g*1024+n]
// per-CTA publication line: words 0..7 = h fp32 bits, word 8 = flag, pad to 128B
__device__ __align__(128) unsigned g_pub[2][NCTA][32];

// ---------------- helpers ----------------
__device__ __forceinline__ float4 ld_cg_f4(const float4* p) {
    float4 v;
    asm volatile("ld.global.cg.v4.f32 {%0,%1,%2,%3}, [%4];"
                 : "=f"(v.x), "=f"(v.y), "=f"(v.z), "=f"(v.w) : "l"(p) : "memory");
    return v;
}
__device__ __forceinline__ void st_cg_u32(unsigned* p, unsigned v) {
    asm volatile("st.global.cg.b32 [%0], %1;" :: "l"(p), "r"(v) : "memory");
}
__device__ __forceinline__ unsigned ld_acq(const unsigned* p) {
    unsigned v;
    asm volatile("ld.acquire.gpu.b32 %0, [%1];" : "=r"(v) : "l"(p) : "memory");
    return v;
}
__device__ __forceinline__ void st_rel(unsigned* p, unsigned v) {
    asm volatile("st.release.gpu.b32 [%0], %1;" :: "l"(p), "r"(v) : "memory");
}
// fast activations (MUFU-based; validated passing at 3.6e-7)
__device__ __forceinline__ float sigf(float x) {
    return __fdividef(1.0f, 1.0f + __expf(-x));
}
__device__ __forceinline__ float tanh_f(float x) {
    float a = fabsf(x);
    float e = __expf(-2.0f * a);
    float t = __fdividef(1.0f - e, 1.0f + e);
    return copysignf(t, x);
}

// Pick X among three same-sized candidates (content-based, deterministic)
__device__ __forceinline__ const float* pick_x(const float* a, const float* b,
                                               const float* c) {
    bool na = false, nb = false;
    for (int i = 0; i < 64; i++) { na |= (a[i] < 0.0f); nb |= (b[i] < 0.0f); }
    return na ? a : (nb ? b : c);
}

// =====================================================================
// Kernel 1: xproj GEMM, STANDARD layout (unchanged from passing rounds).
// =====================================================================
__global__ __launch_bounds__(256, 2) void xproj_kernel(
    const float* __restrict__ xc0, const float* __restrict__ xc1,
    const float* __restrict__ xc2, const float* __restrict__ Wih,
    const float* __restrict__ b0, const float* __restrict__ b1)
{
    __shared__ float As[8][128];
    __shared__ float Bs[8][128];

    const float* X = pick_x(xc0, xc1, xc2);

    const int tid = threadIdx.x;
    const int tx = tid & 15;
    const int ty = tid >> 4;
    const int t0 = blockIdx.y * 128;
    const int R0 = blockIdx.x * 128;

    const int lrow = tid >> 1;
    const int lk4  = (tid & 1) * 4;
    const float* pA = X   + (size_t)(t0 + lrow) * INDIM + lk4;
    const float* pB = Wih + (size_t)(R0 + lrow) * INDIM + lk4;

    float acc[8][8];
    #pragma unroll
    for (int i = 0; i < 8; i++)
        #pragma unroll
        for (int j = 0; j < 8; j++) acc[i][j] = 0.0f;

    float4 ra = *(const float4*)pA;
    float4 rb = *(const float4*)pB;

    for (int k0 = 0; k0 < INDIM; k0 += 8) {
        __syncthreads();
        As[lk4 + 0][lrow] = ra.x; As[lk4 + 1][lrow] = ra.y;
        As[lk4 + 2][lrow] = ra.z; As[lk4 + 3][lrow] = ra.w;
        Bs[lk4 + 0][lrow] = rb.x; Bs[lk4 + 1][lrow] = rb.y;
        Bs[lk4 + 2][lrow] = rb.z; Bs[lk4 + 3][lrow] = rb.w;
        __syncthreads();
        if (k0 + 8 < INDIM) {
            ra = *(const float4*)(pA + k0 + 8);
            rb = *(const float4*)(pB + k0 + 8);
        }
        #pragma unroll
        for (int kk = 0; kk < 8; kk++) {
            float a[8], b[8];
            *(float4*)&a[0] = *(const float4*)&As[kk][ty * 8];
            *(float4*)&a[4] = *(const float4*)&As[kk][ty * 8 + 4];
            *(float4*)&b[0] = *(const float4*)&Bs[kk][tx * 8];
            *(float4*)&b[4] = *(const float4*)&Bs[kk][tx * 8 + 4];
            #pragma unroll
            for (int i = 0; i < 8; i++)
                #pragma unroll
                for (int j = 0; j < 8; j++)
                    acc[i][j] = fmaf(a[i], b[j], acc[i][j]);
        }
    }

    const int Rc = R0 + tx * 8;
    float bias[8];
    #pragma unroll
    for (int j = 0; j < 8; j++) bias[j] = b0[Rc + j] + b1[Rc + j];

    #pragma unroll
    for (int i = 0; i < 8; i++) {
        float v[8];
        #pragma unroll
        for (int j = 0; j < 8; j++) v[j] = acc[i][j] + bias[j];
        float* dst = g_xp + (size_t)(t0 + ty * 8 + i) * G4 + Rc;
        *(float4*)(dst)     = make_float4(v[0], v[1], v[2], v[3]);
        *(float4*)(dst + 4) = make_float4(v[4], v[5], v[6], v[7]);
    }
}

// =====================================================================
// Kernel 2: persistent recurrence. 128 CTAs x 256 threads.
// R12 skeleton (scalar FFMA dots, acquire-polls) with early per-warp
// publication: lane0 of warp w stores h directly into the CTA's packed
// 128B pub line BEFORE the barrier (8 parallel commits overlap the bar),
// then tid0 releases only the 4B flag. store -> bar -> release -> acquire
// is the R7-proven causality pattern.
// =====================================================================
__global__ __launch_bounds__(256, 1) void rnn_kernel(
    const float* __restrict__ Whh, const float* __restrict__ Wlin,
    const float* __restrict__ blin, float* __restrict__ out)
{
    __shared__ float smh[HDIM];   // h_{t-1}, identity layout

    const int tid = threadIdx.x;
    const int w = tid >> 5, l = tid & 31;
    const int n = blockIdx.x * 8 + w;

    // ---- load W_hh into registers as float4 (coalesced, one-time) ----
    // lane l covers cols 4l+128j (j=0..7) for each gate row of h-index n
    float4 wq0[8], wq1[8], wq2[8], wq3[8];
    {
        const float* r0 = Whh + (size_t)(0 * HDIM + n) * HDIM + 4 * l;
        const float* r1 = Whh + (size_t)(1 * HDIM + n) * HDIM + 4 * l;
        const float* r2 = Whh + (size_t)(2 * HDIM + n) * HDIM + 4 * l;
        const float* r3 = Whh + (size_t)(3 * HDIM + n) * HDIM + 4 * l;
        #pragma unroll
        for (int j = 0; j < 8; j++) {
            wq0[j] = __ldg((const float4*)(r0 + 128 * j));
            wq1[j] = __ldg((const float4*)(r1 + 128 * j));
            wq2[j] = __ldg((const float4*)(r2 + 128 * j));
            wq3[j] = __ldg((const float4*)(r3 + 128 * j));
        }
    }

    smh[tid] = 0.0f; smh[tid + 256] = 0.0f;
    smh[tid + 512] = 0.0f; smh[tid + 768] = 0.0f;   // h_{-1} = 0
    float c = 0.0f;

    // prefetch xp for t=0 (lane 0 of each warp)
    float xi = 0.f, xf = 0.f, xg = 0.f, xo = 0.f;
    if (l == 0) {
        const float* xb = g_xp + n;
        xi = __ldcg(xb);
        xf = __ldcg(xb + HDIM);
        xg = __ldcg(xb + 2 * HDIM);
        xo = __ldcg(xb + 3 * HDIM);
    }
    __syncthreads();

    for (int t = 0; t < TSTEPS; t++) {
        // issue next step's xp prefetch (overlaps dots + sync below)
        float nxi = 0.f, nxf = 0.f, nxg = 0.f, nxo = 0.f;
        if (l == 0 && t + 1 < TSTEPS) {
            const float* xb = g_xp + (size_t)(t + 1) * G4 + n;
            nxi = __ldcg(xb);
            nxf = __ldcg(xb + HDIM);
            nxg = __ldcg(xb + 2 * HDIM);
            nxo = __ldcg(xb + 3 * HDIM);
        }

        // 4 gate dot-products over h_{t-1}: 8x LDS.128, 128 scalar FFMA
        float s0 = 0.f, s1 = 0.f, s2 = 0.f, s3 = 0.f;
        #pragma unroll
        for (int j = 0; j < 8; j++) {
            float4 h4 = *(const float4*)&smh[4 * l + 128 * j];
            s0 = fmaf(wq0[j].x, h4.x, s0); s0 = fmaf(wq0[j].y, h4.y, s0);
            s0 = fmaf(wq0[j].z, h4.z, s0); s0 = fmaf(wq0[j].w, h4.w, s0);
            s1 = fmaf(wq1[j].x, h4.x, s1); s1 = fmaf(wq1[j].y, h4.y, s1);
            s1 = fmaf(wq1[j].z, h4.z, s1); s1 = fmaf(wq1[j].w, h4.w, s1);
            s2 = fmaf(wq2[j].x, h4.x, s2); s2 = fmaf(wq2[j].y, h4.y, s2);
            s2 = fmaf(wq2[j].z, h4.z, s2); s2 = fmaf(wq2[j].w, h4.w, s2);
            s3 = fmaf(wq3[j].x, h4.x, s3); s3 = fmaf(wq3[j].y, h4.y, s3);
            s3 = fmaf(wq3[j].z, h4.z, s3); s3 = fmaf(wq3[j].w, h4.w, s3);
        }
        #pragma unroll
        for (int off = 16; off > 0; off >>= 1) {
            s0 += __shfl_xor_sync(0xffffffffu, s0, off);
            s1 += __shfl_xor_sync(0xffffffffu, s1, off);
            s2 += __shfl_xor_sync(0xffffffffu, s2, off);
            s3 += __shfl_xor_sync(0xffffffffu, s3, off);
        }

        // activations (warp-redundant; xp broadcast from lane 0)
        float gi = sigf(s0 + __shfl_sync(0xffffffffu, xi, 0));
        float gf = sigf(s1 + __shfl_sync(0xffffffffu, xf, 0));
        float gg = tanh_f(s2 + __shfl_sync(0xffffffffu, xg, 0));
        float go = sigf(s3 + __shfl_sync(0xffffffffu, xo, 0));
        c = gf * c + gi * gg;
        float hn = go * tanh_f(c);

        // EARLY publication: lane0 of warp w stores h into the packed line
        // immediately -> 8 parallel L2 commits overlap slower warps + bar
        if (l == 0)
            st_cg_u32(&g_pub[t & 1][blockIdx.x][w], __float_as_uint(hn));
        __syncthreads();                 // smh reads done AND all 8 h issued

        // tid0 releases the flag (orders the CTA's pre-bar stores, R7 pattern)
        if (tid == 0)
            st_rel(&g_pub[t & 1][blockIdx.x][8], (unsigned)(t + 1));

        // threads 0..127: acquire-poll source CTA (=tid)'s flag, then load
        // that line's 8 h (L2-hot, same line as flag) and stage to smem
        if (tid < NCTA) {
            const unsigned* base = &g_pub[t & 1][tid][0];
            while (ld_acq(base + 8) != (unsigned)(t + 1)) { }
            float4 a = ld_cg_f4((const float4*)base);
            float4 b = ld_cg_f4((const float4*)(base + 4));
            *(float4*)&smh[8 * tid]     = a;
            *(float4*)&smh[8 * tid + 4] = b;
        }
        __syncthreads();                 // smh complete for next step

        xi = nxi; xf = nxf; xg = nxg; xo = nxo;
    }

    // ---- final linear + sigmoid on CTA 0 (smh holds h_{T-1}) ----
    if (blockIdx.x == 0) {
        #pragma unroll 1
        for (int o = w; o < OUTDIM; o += 8) {
            const float* wl = Wlin + (size_t)o * HDIM;
            float acc = 0.0f;
            #pragma unroll
            for (int j = 0; j < 32; j++) {
                int k = l + 32 * j;
                acc = fmaf(wl[k], smh[k], acc);
            }
            #pragma unroll
            for (int off = 16; off > 0; off >>= 1)
                acc += __shfl_xor_sync(0xffffffffu, acc, off);
            if (l == 0)
                out[o] = __fdividef(1.0f, 1.0f + __expf(-(acc + blin[o])));
        }
    }
}

// =====================================================================
// Host: resolve inputs BY SIZE (ordering-proof).
// =====================================================================
extern "C" void kernel_launch(void* const* d_in, const int* in_sizes, int n_in,
                              void* d_out, int out_size)
{
    const float* cand[3] = {nullptr, nullptr, nullptr};
    int nc = 0;
    const float* Wih = nullptr;
    const float* Whh = nullptr;
    const float* bsum[2] = {nullptr, nullptr};
    int nb = 0;
    const float* Wlin = nullptr;
    const float* blin = nullptr;

    for (int i = 0; i < n_in; i++) {
        const float* p = (const float*)d_in[i];
        switch (in_sizes[i]) {
            case 8388608: if (nc < 3) cand[nc++] = p; break;
            case 2097152: Wih = p; break;
            case 4194304: Whh = p; break;
            case 4096:    if (nb < 2) bsum[nb++] = p; break;
            case 65536:   Wlin = p; break;
            case 64:      blin = p; break;
            default: break; // dt (16384) unused
        }
    }
    float* out = (float*)d_out;

    dim3 ggrid(G4 / 128, TSTEPS / 128);       // 32 x 128 tiles
    xproj_kernel<<<ggrid, 256>>>(cand[0], cand[1], cand[2], Wih, bsum[0], bsum[1]);
    rnn_kernel<<<NCTA, 256>>>(Whh, Wlin, blin, out);
}